// round 14
// baseline (speedup 1.0000x reference)
#include <cuda_runtime.h>
#include <cstddef>

// SNN: 2-2-2 spiking net, B=500k independent elements, T=32 steps.
// History:
//   R3:  1 elem/thread, float2 stcs, 1954 CTAs   57.8us  (best)  DRAM 70.9%
//   R4:  pairs/float4, 977 CTAs                  67.6us  (wave tail)
//   R5:  grid-stride 888                         63.6us
//   R8:  4x8-step chunks                         62.0us  (issue-bound)
//   R9:  2x16-step chunks, LPT                   60.1us
//   R10: L2-residency hint                       62.0us  (no retention)
//   R11: pairs+halves, STG.128                   61.6us  (width no help)
// Conclusion: all variants pin at ~6.5-6.6TB/s effective write BW (the HBM
// pure-write wall). This round: R3's exact structure + strictly-free trims:
//   - reset-carry (reset at t == spike at t-1; exact since s in {0,1}):
//     fewer FSETPs, fewer regs (40->32), occupancy 65%->84%
//   - 32-bit indexing w/ pointer increments (TB=16M fits int)
//
// FP association mirrors XLA exactly (verified rel_err==0):
//   dot:  acc = fma(x1, w[j][1], rnd(x0*w[j][0]));  bias: cur = acc + b[j]
//   mem:  ((beta*mem + cur) - reset) with separate rn ops
//
// Output layout: [spk1 | spk2 | mem2], each [T,B,2] float32.

#define SNN_LOAD_PARAMS()                                                       \
    const float w1_00 = __ldg(fc1_w + 0), w1_01 = __ldg(fc1_w + 1);             \
    const float w1_10 = __ldg(fc1_w + 2), w1_11 = __ldg(fc1_w + 3);             \
    const float b1_0  = __ldg(fc1_b + 0), b1_1  = __ldg(fc1_b + 1);             \
    const float w2_00 = __ldg(fc2_w + 0), w2_01 = __ldg(fc2_w + 1);             \
    const float w2_10 = __ldg(fc2_w + 2), w2_11 = __ldg(fc2_w + 3);             \
    const float b2_0  = __ldg(fc2_b + 0), b2_1  = __ldg(fc2_b + 1);             \
    const float bt1   = fminf(fmaxf(__ldg(beta1), 0.f), 1.f);                   \
    const float bt2   = fminf(fmaxf(__ldg(beta2), 0.f), 1.f);                   \
    const float th1   = __ldg(thr1);                                            \
    const float th2   = __ldg(thr2)

template<int T_STEPS>
__global__ __launch_bounds__(256)
void snn_final(const float2* __restrict__ x,
               const float* __restrict__ fc1_w, const float* __restrict__ fc1_b,
               const float* __restrict__ beta1, const float* __restrict__ thr1,
               const float* __restrict__ fc2_w, const float* __restrict__ fc2_b,
               const float* __restrict__ beta2, const float* __restrict__ thr2,
               float2* __restrict__ out, int B, int T_dyn)
{
    const int b = blockIdx.x * blockDim.x + threadIdx.x;
    if (b >= B) return;

    SNN_LOAD_PARAMS();

    const float2 xv = __ldg(&x[b]);
    const float cur1_0 = __fadd_rn(__fmaf_rn(xv.y, w1_01, __fmul_rn(xv.x, w1_00)), b1_0);
    const float cur1_1 = __fadd_rn(__fmaf_rn(xv.y, w1_11, __fmul_rn(xv.x, w1_10)), b1_1);

    float mem1_0 = 0.f, mem1_1 = 0.f, mem2_0 = 0.f, mem2_1 = 0.f;
    // "previous spike" carry; at t=0 the reference computes reset from mem=0:
    // Heaviside(0 - th). Exactly reproduced here.
    float s1_0 = (0.f > th1) ? 1.f : 0.f, s1_1 = s1_0;
    float s2_0 = (0.f > th2) ? 1.f : 0.f, s2_1 = s2_0;

    const int T = (T_STEPS > 0) ? T_STEPS : T_dyn;
    const int TB = T * B;               // 16M floats2 per array: fits int
    // Per-array pointers advanced by B each step: pure 32-bit increments.
    float2* __restrict__ p_spk1 = out + b;
    float2* __restrict__ p_spk2 = out + (TB + b);
    float2* __restrict__ p_mem2 = out + (2 * TB + b);

#pragma unroll
    for (int t = 0; t < T; t++) {
        // reset at step t == spike at step t-1 (exact: s in {0,1})
        const float r1_0 = s1_0 != 0.f ? th1 : 0.f;
        const float r1_1 = s1_1 != 0.f ? th1 : 0.f;
        mem1_0 = __fsub_rn(__fadd_rn(__fmul_rn(bt1, mem1_0), cur1_0), r1_0);
        mem1_1 = __fsub_rn(__fadd_rn(__fmul_rn(bt1, mem1_1), cur1_1), r1_1);
        s1_0 = (mem1_0 > th1) ? 1.f : 0.f;
        s1_1 = (mem1_1 > th1) ? 1.f : 0.f;

        const float cur2_0 = __fadd_rn(__fmaf_rn(s1_1, w2_01, __fmul_rn(s1_0, w2_00)), b2_0);
        const float cur2_1 = __fadd_rn(__fmaf_rn(s1_1, w2_11, __fmul_rn(s1_0, w2_10)), b2_1);

        const float r2_0 = s2_0 != 0.f ? th2 : 0.f;
        const float r2_1 = s2_1 != 0.f ? th2 : 0.f;
        mem2_0 = __fsub_rn(__fadd_rn(__fmul_rn(bt2, mem2_0), cur2_0), r2_0);
        mem2_1 = __fsub_rn(__fadd_rn(__fmul_rn(bt2, mem2_1), cur2_1), r2_1);
        s2_0 = (mem2_0 > th2) ? 1.f : 0.f;
        s2_1 = (mem2_1 > th2) ? 1.f : 0.f;

        __stcs(p_spk1, make_float2(s1_0, s1_1));
        __stcs(p_spk2, make_float2(s2_0, s2_1));
        __stcs(p_mem2, make_float2(mem2_0, mem2_1));
        p_spk1 += B;
        p_spk2 += B;
        p_mem2 += B;
    }
}

extern "C" void kernel_launch(void* const* d_in, const int* in_sizes, int n_in,
                              void* d_out, int out_size) {
    const float2* x     = (const float2*)d_in[0];
    const float*  fc1_w = (const float*)d_in[1];
    const float*  fc1_b = (const float*)d_in[2];
    const float*  beta1 = (const float*)d_in[3];
    const float*  thr1  = (const float*)d_in[4];
    const float*  fc2_w = (const float*)d_in[5];
    const float*  fc2_b = (const float*)d_in[6];
    const float*  beta2 = (const float*)d_in[7];
    const float*  thr2  = (const float*)d_in[8];

    const int B = in_sizes[0] / 2;          // x is [B, 2]
    const int T = out_size / (6 * B);       // out = 3 arrays of [T, B, 2]

    const int threads = 256;
    const int blocks = (B + threads - 1) / threads;

    if (T == 32) {
        snn_final<32><<<blocks, threads>>>(x, fc1_w, fc1_b, beta1, thr1,
                                           fc2_w, fc2_b, beta2, thr2,
                                           (float2*)d_out, B, T);
    } else {
        snn_final<0><<<blocks, threads>>>(x, fc1_w, fc1_b, beta1, thr1,
                                          fc2_w, fc2_b, beta2, thr2,
                                          (float2*)d_out, B, T);
    }
}

// round 15
// speedup vs baseline: 1.3945x; 1.3945x over previous
#include <cuda_runtime.h>
#include <cstddef>

// SNN: 2-2-2 spiking net, B=500k independent batch elements, T=32 steps.
// cur1 is time-invariant -> computed once per thread. Each thread runs the
// whole recurrence in registers and streams out spk1/spk2/mem2 per step.
//
// FP association carefully mirrors XLA's lowering:
//   dot:  acc = fma(x1, w[j][1], rnd(x0 * w[j][0]))   (reduce over k)
//   bias: cur = acc + b[j]                            (separate add)
// beta=0.5 makes the mem recurrence fma-insensitive (exact product).
//
// FINAL (R15 = R3 verbatim, measured 57.8us, rel_err 0.0):
// exploration showed every deviation regresses —
//   R4  pairs/float4 977 CTAs   67.6us (wave tail)
//   R5  grid-stride 888         63.6us (quantization)
//   R8  4x8 chunks              62.0us (issue-bound)
//   R9  2x16 chunks LPT         60.1us
//   R10 L2-residency hint       62.0us (no retention across replays)
//   R11 pairs+halves STG.128    61.6us (width-insensitive write wall)
//   R14 reset-carry+ptr-incr    82.0us (occ 80% -> L1tex queue jam)
// R3's 40-reg / 65%-occ / float2-stcs shape sits at the HBM pure-write
// ceiling (~6.6TB/s effective, 83% of spec). Keep it.
//
// Output layout (concatenated, matching reference return order):
//   [0,              T*B*2)   spk1_rec  [T,B,2]
//   [T*B*2,        2*T*B*2)   spk2_rec  [T,B,2]
//   [2*T*B*2,      3*T*B*2)   mem2_rec  [T,B,2]

template<int T_STEPS>
__global__ __launch_bounds__(256)
void snn_kernel(const float2* __restrict__ x,
                const float* __restrict__ fc1_w, const float* __restrict__ fc1_b,
                const float* __restrict__ beta1, const float* __restrict__ thr1,
                const float* __restrict__ fc2_w, const float* __restrict__ fc2_b,
                const float* __restrict__ beta2, const float* __restrict__ thr2,
                float2* __restrict__ out, int B, int T_dyn)
{
    const int b = blockIdx.x * blockDim.x + threadIdx.x;
    if (b >= B) return;

    // Broadcast scalar params (uniform across all threads; L1-cached)
    const float w1_00 = __ldg(fc1_w + 0), w1_01 = __ldg(fc1_w + 1);
    const float w1_10 = __ldg(fc1_w + 2), w1_11 = __ldg(fc1_w + 3);
    const float b1_0  = __ldg(fc1_b + 0), b1_1  = __ldg(fc1_b + 1);
    const float w2_00 = __ldg(fc2_w + 0), w2_01 = __ldg(fc2_w + 1);
    const float w2_10 = __ldg(fc2_w + 2), w2_11 = __ldg(fc2_w + 3);
    const float b2_0  = __ldg(fc2_b + 0), b2_1  = __ldg(fc2_b + 1);
    const float bt1   = fminf(fmaxf(__ldg(beta1), 0.f), 1.f);
    const float bt2   = fminf(fmaxf(__ldg(beta2), 0.f), 1.f);
    const float th1   = __ldg(thr1);
    const float th2   = __ldg(thr2);

    const float2 xv = __ldg(&x[b]);
    // cur1[j] = (x0*W1[j][0] fma-reduced with x1*W1[j][1]) + b1[j]
    const float cur1_0 = __fadd_rn(__fmaf_rn(xv.y, w1_01, __fmul_rn(xv.x, w1_00)), b1_0);
    const float cur1_1 = __fadd_rn(__fmaf_rn(xv.y, w1_11, __fmul_rn(xv.x, w1_10)), b1_1);

    float mem1_0 = 0.f, mem1_1 = 0.f;
    float mem2_0 = 0.f, mem2_1 = 0.f;

    const int T = (T_STEPS > 0) ? T_STEPS : T_dyn;
    const size_t TB = (size_t)T * (size_t)B;
    float2* __restrict__ o_spk1 = out;
    float2* __restrict__ o_spk2 = out + TB;
    float2* __restrict__ o_mem2 = out + 2 * TB;

#pragma unroll
    for (int t = 0; t < T; t++) {
        // reset from PREVIOUS mem (forward: just the Heaviside)
        const float r1_0 = (mem1_0 > th1) ? th1 : 0.f;
        const float r1_1 = (mem1_1 > th1) ? th1 : 0.f;
        // mem1 = (b1*mem1 + cur1) - r1*th1 ; b1*mem1 exact (beta=0.5),
        // r1 already equals r*th1 with exact product.
        mem1_0 = __fsub_rn(__fadd_rn(__fmul_rn(bt1, mem1_0), cur1_0), r1_0);
        mem1_1 = __fsub_rn(__fadd_rn(__fmul_rn(bt1, mem1_1), cur1_1), r1_1);
        const float s1_0 = (mem1_0 > th1) ? 1.f : 0.f;
        const float s1_1 = (mem1_1 > th1) ? 1.f : 0.f;

        // cur2[j] = (s0*W2[j][0] fma-reduced with s1*W2[j][1]) + b2[j]
        const float cur2_0 = __fadd_rn(__fmaf_rn(s1_1, w2_01, __fmul_rn(s1_0, w2_00)), b2_0);
        const float cur2_1 = __fadd_rn(__fmaf_rn(s1_1, w2_11, __fmul_rn(s1_0, w2_10)), b2_1);

        const float r2_0 = (mem2_0 > th2) ? th2 : 0.f;
        const float r2_1 = (mem2_1 > th2) ? th2 : 0.f;
        mem2_0 = __fsub_rn(__fadd_rn(__fmul_rn(bt2, mem2_0), cur2_0), r2_0);
        mem2_1 = __fsub_rn(__fadd_rn(__fmul_rn(bt2, mem2_1), cur2_1), r2_1);
        const float s2_0 = (mem2_0 > th2) ? 1.f : 0.f;
        const float s2_1 = (mem2_1 > th2) ? 1.f : 0.f;

        const size_t idx = (size_t)t * (size_t)B + (size_t)b;
        __stcs(&o_spk1[idx], make_float2(s1_0, s1_1));
        __stcs(&o_spk2[idx], make_float2(s2_0, s2_1));
        __stcs(&o_mem2[idx], make_float2(mem2_0, mem2_1));
    }
}

extern "C" void kernel_launch(void* const* d_in, const int* in_sizes, int n_in,
                              void* d_out, int out_size) {
    const float2* x     = (const float2*)d_in[0];
    const float*  fc1_w = (const float*)d_in[1];
    const float*  fc1_b = (const float*)d_in[2];
    const float*  beta1 = (const float*)d_in[3];
    const float*  thr1  = (const float*)d_in[4];
    const float*  fc2_w = (const float*)d_in[5];
    const float*  fc2_b = (const float*)d_in[6];
    const float*  beta2 = (const float*)d_in[7];
    const float*  thr2  = (const float*)d_in[8];

    const int B = in_sizes[0] / 2;          // x is [B, 2]
    const int T = out_size / (6 * B);       // out = 3 arrays of [T, B, 2]

    const int threads = 256;
    const int blocks = (B + threads - 1) / threads;

    if (T == 32) {
        snn_kernel<32><<<blocks, threads>>>(x, fc1_w, fc1_b, beta1, thr1,
                                            fc2_w, fc2_b, beta2, thr2,
                                            (float2*)d_out, B, T);
    } else {
        snn_kernel<0><<<blocks, threads>>>(x, fc1_w, fc1_b, beta1, thr1,
                                           fc2_w, fc2_b, beta2, thr2,
                                           (float2*)d_out, B, T);
    }
}

// round 16
// speedup vs baseline: 1.4082x; 1.0099x over previous
#include <cuda_runtime.h>
#include <cstddef>

// SNN: 2-2-2 spiking net, B=500k independent batch elements, T=32 steps.
// cur1 is time-invariant -> computed once per thread. Each thread runs the
// whole recurrence in registers and streams out spk1/spk2/mem2 per step.
//
// FP association carefully mirrors XLA's lowering:
//   dot:  acc = fma(x1, w[j][1], rnd(x0 * w[j][0]))   (reduce over k)
//   bias: cur = acc + b[j]                            (separate add)
// beta=0.5 makes the mem recurrence fma-insensitive (exact product).
//
// FINAL (== R3, measured 57.8us / 58.8us across runs, rel_err 0.0):
// the kernel is at the HBM pure-write wall (384MB stores / 57.8us =
// 6.6TB/s = 83% of spec). Full exploration matrix regressed:
//   R4  pairs/float4 977 CTAs   67.6us (wave tail)
//   R5  grid-stride 888         63.6us (quantization)
//   R8  4x8 chunks              62.0us (issue-bound)
//   R9  2x16 chunks LPT         60.1us
//   R10 L2-residency hint       62.0us (no retention across replays)
//   R11 pairs+halves STG.128    61.6us (width-insensitive write wall)
//   R14 reset-carry+ptr-incr    82.0us (occ 80% -> L1tex queue jam)
// R3's 40-reg / 65%-occ / 6-CTA/SM / float2-stcs shape is load-matched to
// the store path. Keep it.
//
// Output layout (concatenated, matching reference return order):
//   [0,              T*B*2)   spk1_rec  [T,B,2]
//   [T*B*2,        2*T*B*2)   spk2_rec  [T,B,2]
//   [2*T*B*2,      3*T*B*2)   mem2_rec  [T,B,2]

template<int T_STEPS>
__global__ __launch_bounds__(256)
void snn_kernel(const float2* __restrict__ x,
                const float* __restrict__ fc1_w, const float* __restrict__ fc1_b,
                const float* __restrict__ beta1, const float* __restrict__ thr1,
                const float* __restrict__ fc2_w, const float* __restrict__ fc2_b,
                const float* __restrict__ beta2, const float* __restrict__ thr2,
                float2* __restrict__ out, int B, int T_dyn)
{
    const int b = blockIdx.x * blockDim.x + threadIdx.x;
    if (b >= B) return;

    // Broadcast scalar params (uniform across all threads; L1-cached)
    const float w1_00 = __ldg(fc1_w + 0), w1_01 = __ldg(fc1_w + 1);
    const float w1_10 = __ldg(fc1_w + 2), w1_11 = __ldg(fc1_w + 3);
    const float b1_0  = __ldg(fc1_b + 0), b1_1  = __ldg(fc1_b + 1);
    const float w2_00 = __ldg(fc2_w + 0), w2_01 = __ldg(fc2_w + 1);
    const float w2_10 = __ldg(fc2_w + 2), w2_11 = __ldg(fc2_w + 3);
    const float b2_0  = __ldg(fc2_b + 0), b2_1  = __ldg(fc2_b + 1);
    const float bt1   = fminf(fmaxf(__ldg(beta1), 0.f), 1.f);
    const float bt2   = fminf(fmaxf(__ldg(beta2), 0.f), 1.f);
    const float th1   = __ldg(thr1);
    const float th2   = __ldg(thr2);

    const float2 xv = __ldg(&x[b]);
    // cur1[j] = (x0*W1[j][0] fma-reduced with x1*W1[j][1]) + b1[j]
    const float cur1_0 = __fadd_rn(__fmaf_rn(xv.y, w1_01, __fmul_rn(xv.x, w1_00)), b1_0);
    const float cur1_1 = __fadd_rn(__fmaf_rn(xv.y, w1_11, __fmul_rn(xv.x, w1_10)), b1_1);

    float mem1_0 = 0.f, mem1_1 = 0.f;
    float mem2_0 = 0.f, mem2_1 = 0.f;

    const int T = (T_STEPS > 0) ? T_STEPS : T_dyn;
    const size_t TB = (size_t)T * (size_t)B;
    float2* __restrict__ o_spk1 = out;
    float2* __restrict__ o_spk2 = out + TB;
    float2* __restrict__ o_mem2 = out + 2 * TB;

#pragma unroll
    for (int t = 0; t < T; t++) {
        // reset from PREVIOUS mem (forward: just the Heaviside)
        const float r1_0 = (mem1_0 > th1) ? th1 : 0.f;
        const float r1_1 = (mem1_1 > th1) ? th1 : 0.f;
        // mem1 = (b1*mem1 + cur1) - r1*th1 ; b1*mem1 exact (beta=0.5),
        // r1 already equals r*th1 with exact product.
        mem1_0 = __fsub_rn(__fadd_rn(__fmul_rn(bt1, mem1_0), cur1_0), r1_0);
        mem1_1 = __fsub_rn(__fadd_rn(__fmul_rn(bt1, mem1_1), cur1_1), r1_1);
        const float s1_0 = (mem1_0 > th1) ? 1.f : 0.f;
        const float s1_1 = (mem1_1 > th1) ? 1.f : 0.f;

        // cur2[j] = (s0*W2[j][0] fma-reduced with s1*W2[j][1]) + b2[j]
        const float cur2_0 = __fadd_rn(__fmaf_rn(s1_1, w2_01, __fmul_rn(s1_0, w2_00)), b2_0);
        const float cur2_1 = __fadd_rn(__fmaf_rn(s1_1, w2_11, __fmul_rn(s1_0, w2_10)), b2_1);

        const float r2_0 = (mem2_0 > th2) ? th2 : 0.f;
        const float r2_1 = (mem2_1 > th2) ? th2 : 0.f;
        mem2_0 = __fsub_rn(__fadd_rn(__fmul_rn(bt2, mem2_0), cur2_0), r2_0);
        mem2_1 = __fsub_rn(__fadd_rn(__fmul_rn(bt2, mem2_1), cur2_1), r2_1);
        const float s2_0 = (mem2_0 > th2) ? 1.f : 0.f;
        const float s2_1 = (mem2_1 > th2) ? 1.f : 0.f;

        const size_t idx = (size_t)t * (size_t)B + (size_t)b;
        __stcs(&o_spk1[idx], make_float2(s1_0, s1_1));
        __stcs(&o_spk2[idx], make_float2(s2_0, s2_1));
        __stcs(&o_mem2[idx], make_float2(mem2_0, mem2_1));
    }
}

extern "C" void kernel_launch(void* const* d_in, const int* in_sizes, int n_in,
                              void* d_out, int out_size) {
    const float2* x     = (const float2*)d_in[0];
    const float*  fc1_w = (const float*)d_in[1];
    const float*  fc1_b = (const float*)d_in[2];
    const float*  beta1 = (const float*)d_in[3];
    const float*  thr1  = (const float*)d_in[4];
    const float*  fc2_w = (const float*)d_in[5];
    const float*  fc2_b = (const float*)d_in[6];
    const float*  beta2 = (const float*)d_in[7];
    const float*  thr2  = (const float*)d_in[8];

    const int B = in_sizes[0] / 2;          // x is [B, 2]
    const int T = out_size / (6 * B);       // out = 3 arrays of [T, B, 2]

    const int threads = 256;
    const int blocks = (B + threads - 1) / threads;

    if (T == 32) {
        snn_kernel<32><<<blocks, threads>>>(x, fc1_w, fc1_b, beta1, thr1,
                                            fc2_w, fc2_b, beta2, thr2,
                                            (float2*)d_out, B, T);
    } else {
        snn_kernel<0><<<blocks, threads>>>(x, fc1_w, fc1_b, beta1, thr1,
                                           fc2_w, fc2_b, beta2, thr2,
                                           (float2*)d_out, B, T);
    }
}

// round 17
// speedup vs baseline: 1.4184x; 1.0072x over previous
#include <cuda_runtime.h>
#include <cstddef>

// SNN: 2-2-2 spiking net, B=500k independent batch elements, T=32 steps.
// cur1 is time-invariant -> computed once per thread. Each thread runs the
// whole recurrence in registers and streams out spk1/spk2/mem2 per step.
//
// FP association mirrors XLA's lowering exactly (rel_err == 0.0):
//   dot:  acc = fma(x1, w[j][1], rnd(x0 * w[j][0]))   (reduce over k)
//   bias: cur = acc + b[j]                            (separate add)
//   mem:  ((beta*mem + cur) - reset) with separate rn ops
//
// FINAL. Measured 57.8 / 58.8 / 58.2 us across runs — at the HBM pure-write
// wall: 384MB mandatory stores / 57.8us = 6.6TB/s = 83% of 8TB/s spec.
// Exploration matrix (all regressed vs this shape):
//   R4  pairs/float4 977 CTAs   67.6us (wave tail)
//   R5  grid-stride 888         63.6us (quantization)
//   R8  4x8 chunks              62.0us (issue-bound)
//   R9  2x16 chunks LPT         60.1us
//   R10 L2-residency hint       62.0us (no retention across replays)
//   R11 pairs+halves STG.128    61.6us (width-insensitive write wall)
//   R14 reset-carry+ptr-incr    82.0us (occ 80% -> L1tex queue jam)
// The 40-reg / 65%-occ / 6-CTA/SM / float2-stcs / 2.2-wave shape is
// load-matched to the store path.
//
// Output layout (concatenated, matching reference return order):
//   [0,              T*B*2)   spk1_rec  [T,B,2]
//   [T*B*2,        2*T*B*2)   spk2_rec  [T,B,2]
//   [2*T*B*2,      3*T*B*2)   mem2_rec  [T,B,2]

template<int T_STEPS>
__global__ __launch_bounds__(256)
void snn_kernel(const float2* __restrict__ x,
                const float* __restrict__ fc1_w, const float* __restrict__ fc1_b,
                const float* __restrict__ beta1, const float* __restrict__ thr1,
                const float* __restrict__ fc2_w, const float* __restrict__ fc2_b,
                const float* __restrict__ beta2, const float* __restrict__ thr2,
                float2* __restrict__ out, int B, int T_dyn)
{
    const int b = blockIdx.x * blockDim.x + threadIdx.x;
    if (b >= B) return;

    // Broadcast scalar params (uniform across all threads; L1-cached)
    const float w1_00 = __ldg(fc1_w + 0), w1_01 = __ldg(fc1_w + 1);
    const float w1_10 = __ldg(fc1_w + 2), w1_11 = __ldg(fc1_w + 3);
    const float b1_0  = __ldg(fc1_b + 0), b1_1  = __ldg(fc1_b + 1);
    const float w2_00 = __ldg(fc2_w + 0), w2_01 = __ldg(fc2_w + 1);
    const float w2_10 = __ldg(fc2_w + 2), w2_11 = __ldg(fc2_w + 3);
    const float b2_0  = __ldg(fc2_b + 0), b2_1  = __ldg(fc2_b + 1);
    const float bt1   = fminf(fmaxf(__ldg(beta1), 0.f), 1.f);
    const float bt2   = fminf(fmaxf(__ldg(beta2), 0.f), 1.f);
    const float th1   = __ldg(thr1);
    const float th2   = __ldg(thr2);

    const float2 xv = __ldg(&x[b]);
    // cur1[j] = (x0*W1[j][0] fma-reduced with x1*W1[j][1]) + b1[j]
    const float cur1_0 = __fadd_rn(__fmaf_rn(xv.y, w1_01, __fmul_rn(xv.x, w1_00)), b1_0);
    const float cur1_1 = __fadd_rn(__fmaf_rn(xv.y, w1_11, __fmul_rn(xv.x, w1_10)), b1_1);

    float mem1_0 = 0.f, mem1_1 = 0.f;
    float mem2_0 = 0.f, mem2_1 = 0.f;

    const int T = (T_STEPS > 0) ? T_STEPS : T_dyn;
    const size_t TB = (size_t)T * (size_t)B;
    float2* __restrict__ o_spk1 = out;
    float2* __restrict__ o_spk2 = out + TB;
    float2* __restrict__ o_mem2 = out + 2 * TB;

#pragma unroll
    for (int t = 0; t < T; t++) {
        // reset from PREVIOUS mem (forward: just the Heaviside)
        const float r1_0 = (mem1_0 > th1) ? th1 : 0.f;
        const float r1_1 = (mem1_1 > th1) ? th1 : 0.f;
        // mem1 = (b1*mem1 + cur1) - r1*th1 ; b1*mem1 exact (beta=0.5),
        // r1 already equals r*th1 with exact product.
        mem1_0 = __fsub_rn(__fadd_rn(__fmul_rn(bt1, mem1_0), cur1_0), r1_0);
        mem1_1 = __fsub_rn(__fadd_rn(__fmul_rn(bt1, mem1_1), cur1_1), r1_1);
        const float s1_0 = (mem1_0 > th1) ? 1.f : 0.f;
        const float s1_1 = (mem1_1 > th1) ? 1.f : 0.f;

        // cur2[j] = (s0*W2[j][0] fma-reduced with s1*W2[j][1]) + b2[j]
        const float cur2_0 = __fadd_rn(__fmaf_rn(s1_1, w2_01, __fmul_rn(s1_0, w2_00)), b2_0);
        const float cur2_1 = __fadd_rn(__fmaf_rn(s1_1, w2_11, __fmul_rn(s1_0, w2_10)), b2_1);

        const float r2_0 = (mem2_0 > th2) ? th2 : 0.f;
        const float r2_1 = (mem2_1 > th2) ? th2 : 0.f;
        mem2_0 = __fsub_rn(__fadd_rn(__fmul_rn(bt2, mem2_0), cur2_0), r2_0);
        mem2_1 = __fsub_rn(__fadd_rn(__fmul_rn(bt2, mem2_1), cur2_1), r2_1);
        const float s2_0 = (mem2_0 > th2) ? 1.f : 0.f;
        const float s2_1 = (mem2_1 > th2) ? 1.f : 0.f;

        const size_t idx = (size_t)t * (size_t)B + (size_t)b;
        __stcs(&o_spk1[idx], make_float2(s1_0, s1_1));
        __stcs(&o_spk2[idx], make_float2(s2_0, s2_1));
        __stcs(&o_mem2[idx], make_float2(mem2_0, mem2_1));
    }
}

extern "C" void kernel_launch(void* const* d_in, const int* in_sizes, int n_in,
                              void* d_out, int out_size) {
    const float2* x     = (const float2*)d_in[0];
    const float*  fc1_w = (const float*)d_in[1];
    const float*  fc1_b = (const float*)d_in[2];
    const float*  beta1 = (const float*)d_in[3];
    const float*  thr1  = (const float*)d_in[4];
    const float*  fc2_w = (const float*)d_in[5];
    const float*  fc2_b = (const float*)d_in[6];
    const float*  beta2 = (const float*)d_in[7];
    const float*  thr2  = (const float*)d_in[8];

    const int B = in_sizes[0] / 2;          // x is [B, 2]
    const int T = out_size / (6 * B);       // out = 3 arrays of [T, B, 2]

    const int threads = 256;
    const int blocks = (B + threads - 1) / threads;

    if (T == 32) {
        snn_kernel<32><<<blocks, threads>>>(x, fc1_w, fc1_b, beta1, thr1,
                                            fc2_w, fc2_b, beta2, thr2,
                                            (float2*)d_out, B, T);
    } else {
        snn_kernel<0><<<blocks, threads>>>(x, fc1_w, fc1_b, beta1, thr1,
                                           fc2_w, fc2_b, beta2, thr2,
                                           (float2*)d_out, B, T);
    }
}